// round 7
// baseline (speedup 1.0000x reference)
#include <cuda_runtime.h>

#define NV 100000
#define NE 1600000
#define HID 64
#define FIN 256
#define TM 32
#define PADA 68
#define NBLK_SCAN 391   // ceil(NV/256)

typedef unsigned long long ull;

// ---------------- scratch (static device globals) ---------------------------
__device__ float g_ns[NV];
__device__ float g_nd[NV];
__device__ int   g_odeg[NV];
__device__ int   g_indeg[NV];
__device__ int   g_rowptr[NV + 1];
__device__ int   g_cur[NV];
__device__ int   g_bsum[512];
__device__ int   g_boff[512];
__device__ int   g_esrc[NE];                  // src ids grouped by dst (CSR)
__device__ float g_hs[(size_t)NV * HID];      // per-layer message table
__device__ float g_agg[(size_t)NV * HID];     // gather destination
__device__ float g_y[(size_t)NV * HID];       // accumulated out @ Wout

// ---------------- f32x2 helpers ----------------------------------------------
__device__ __forceinline__ ull fma2(ull a, ull b, ull c) {
    ull d;
    asm("fma.rn.f32x2 %0, %1, %2, %3;" : "=l"(d) : "l"(a), "l"(b), "l"(c));
    return d;
}
__device__ __forceinline__ ull dup2(float x) {
    ull d;
    asm("mov.b64 %0, {%1, %1};" : "=l"(d) : "f"(x));
    return d;
}
__device__ __forceinline__ float flo(ull u) { return __uint_as_float((unsigned)u); }
__device__ __forceinline__ float fhi(ull u) { return __uint_as_float((unsigned)(u >> 32)); }

// ---------------- degree / CSR build ----------------------------------------
__global__ void k_zero0() {
    int i = blockIdx.x * blockDim.x + threadIdx.x;
    if (i < NV) { g_odeg[i] = 0; g_indeg[i] = 0; }
}

__global__ void k_deg(const int* __restrict__ src, const int* __restrict__ dst) {
    int e = blockIdx.x * blockDim.x + threadIdx.x;
    if (e < NE) {
        atomicAdd(&g_odeg[src[e]], 1);
        atomicAdd(&g_indeg[dst[e]], 1);
    }
}

__global__ void k_norm() {
    int i = blockIdx.x * blockDim.x + threadIdx.x;
    if (i < NV) {
        g_ns[i] = rsqrtf(fmaxf((float)g_odeg[i], 1.f));
        g_nd[i] = rsqrtf(fmaxf((float)g_indeg[i], 1.f));
    }
}

__global__ void __launch_bounds__(256) k_scan1() {
    __shared__ int sm[256];
    int t = threadIdx.x;
    int i = blockIdx.x * 256 + t;
    int v = (i < NV) ? g_indeg[i] : 0;
    sm[t] = v;
    __syncthreads();
    #pragma unroll
    for (int ofs = 1; ofs < 256; ofs <<= 1) {
        int add = (t >= ofs) ? sm[t - ofs] : 0;
        __syncthreads();
        sm[t] += add;
        __syncthreads();
    }
    if (i < NV) g_rowptr[i] = sm[t] - v;
    if (t == 255) g_bsum[blockIdx.x] = sm[255];
}

__global__ void __launch_bounds__(512) k_scan2() {
    __shared__ int sm[512];
    int t = threadIdx.x;
    int v = (t < NBLK_SCAN) ? g_bsum[t] : 0;
    sm[t] = v;
    __syncthreads();
    #pragma unroll
    for (int ofs = 1; ofs < 512; ofs <<= 1) {
        int add = (t >= ofs) ? sm[t - ofs] : 0;
        __syncthreads();
        sm[t] += add;
        __syncthreads();
    }
    g_boff[t] = sm[t] - v;
}

__global__ void k_scan3() {
    int i = blockIdx.x * blockDim.x + threadIdx.x;
    if (i < NV) {
        int r = g_rowptr[i] + g_boff[i >> 8];
        g_rowptr[i] = r;
        g_cur[i] = r;
    }
    if (i == 0) g_rowptr[NV] = NE;
}

__global__ void k_fill(const int* __restrict__ src, const int* __restrict__ dst) {
    int e = blockIdx.x * blockDim.x + threadIdx.x;
    if (e < NE) {
        int pos = atomicAdd(&g_cur[dst[e]], 1);
        g_esrc[pos] = src[e];
    }
}

// ---------------- CSR gather (R4 structure, at LTS roofline) ------------------
__global__ void __launch_bounds__(256)
k_gather_hs() {
    int w = (blockIdx.x * 256 + threadIdx.x) >> 5;
    int lane = threadIdx.x & 31;
    if (w >= NV) return;
    int beg = g_rowptr[w], end = g_rowptr[w + 1];
    const float2* tb = reinterpret_cast<const float2*>(g_hs);
    float2 acc = make_float2(0.f, 0.f);
    int e = beg;
    for (; e + 4 <= end; e += 4) {
        int s0 = g_esrc[e], s1 = g_esrc[e + 1], s2 = g_esrc[e + 2], s3 = g_esrc[e + 3];
        float2 v0 = tb[(size_t)s0 * 32 + lane];
        float2 v1 = tb[(size_t)s1 * 32 + lane];
        float2 v2 = tb[(size_t)s2 * 32 + lane];
        float2 v3 = tb[(size_t)s3 * 32 + lane];
        acc.x += (v0.x + v1.x) + (v2.x + v3.x);
        acc.y += (v0.y + v1.y) + (v2.y + v3.y);
    }
    for (; e < end; e++) {
        int s = g_esrc[e];
        float2 v = tb[(size_t)s * 32 + lane];
        acc.x += v.x; acc.y += v.y;
    }
    reinterpret_cast<float2*>(g_agg)[(size_t)w * 32 + lane] = acc;
}

__global__ void __launch_bounds__(256)
k_gather_out(float* __restrict__ out, const float* __restrict__ bout) {
    int w = (blockIdx.x * 256 + threadIdx.x) >> 5;
    int lane = threadIdx.x & 31;
    if (w >= NV) return;
    int beg = g_rowptr[w], end = g_rowptr[w + 1];
    const float2* tb = reinterpret_cast<const float2*>(g_y);
    float2 acc = reinterpret_cast<const float2*>(bout)[lane];
    int e = beg;
    for (; e + 4 <= end; e += 4) {
        int s0 = g_esrc[e], s1 = g_esrc[e + 1], s2 = g_esrc[e + 2], s3 = g_esrc[e + 3];
        float2 v0 = tb[(size_t)s0 * 32 + lane];
        float2 v1 = tb[(size_t)s1 * 32 + lane];
        float2 v2 = tb[(size_t)s2 * 32 + lane];
        float2 v3 = tb[(size_t)s3 * 32 + lane];
        acc.x += (v0.x + v1.x) + (v2.x + v3.x);
        acc.y += (v0.y + v1.y) + (v2.y + v3.y);
    }
    for (; e < end; e++) {
        int s = g_esrc[e];
        float2 v = tb[(size_t)s * 32 + lane];
        acc.x += v.x; acc.y += v.y;
    }
    reinterpret_cast<float2*>(out)[(size_t)w * 32 + lane] = acc;
}

// ---------------- GEMM 0 v2: hs = ns * (feats @ W0), K=256 -------------------
// M-tile 64, per-thread 4x8 (f32x2 pairs along N). tx=t&7 -> c0=tx*8,
// ty=t>>3 -> m0=ty*4. A padded to 68 (banks: 4*68 % 32 = 16 -> conflict-free-ish)
__global__ void __launch_bounds__(128)
k_gemm0(const float* __restrict__ feats, const float* __restrict__ W0) {
    __shared__ float As[64][PADA];
    __shared__ float Bs[64][64];
    int t = threadIdx.x;
    int tx = t & 7, ty = t >> 3;
    int c0 = tx * 8, m0 = ty * 4;
    int rowBase = blockIdx.x * 64;

    ull acc[4][4];
    #pragma unroll
    for (int i = 0; i < 4; i++)
        #pragma unroll
        for (int j = 0; j < 4; j++) acc[i][j] = 0ull;

    for (int kb = 0; kb < FIN; kb += 64) {
        #pragma unroll
        for (int i = 0; i < 8; i++) {               // A: 64x64 (1024 float4)
            int idx = t + i * 128;
            int m = idx >> 4, k4 = (idx & 15) * 4;
            int rc = rowBase + m; if (rc >= NV) rc = NV - 1;
            *reinterpret_cast<float4*>(&As[m][k4]) =
                *reinterpret_cast<const float4*>(feats + (size_t)rc * FIN + kb + k4);
        }
        #pragma unroll
        for (int i = 0; i < 8; i++) {               // B: 64x64 (1024 float4)
            int idx = t + i * 128;
            int k = idx >> 4, c4 = (idx & 15) * 4;
            *reinterpret_cast<float4*>(&Bs[k][c4]) =
                *reinterpret_cast<const float4*>(W0 + (size_t)(kb + k) * HID + c4);
        }
        __syncthreads();
        #pragma unroll 8
        for (int k = 0; k < 64; k++) {
            ull ad[4];
            #pragma unroll
            for (int i = 0; i < 4; i++) ad[i] = dup2(As[m0 + i][k]);
            ulonglong2 b0 = *reinterpret_cast<const ulonglong2*>(&Bs[k][c0]);
            ulonglong2 b1 = *reinterpret_cast<const ulonglong2*>(&Bs[k][c0 + 4]);
            #pragma unroll
            for (int i = 0; i < 4; i++) {
                acc[i][0] = fma2(ad[i], b0.x, acc[i][0]);
                acc[i][1] = fma2(ad[i], b0.y, acc[i][1]);
                acc[i][2] = fma2(ad[i], b1.x, acc[i][2]);
                acc[i][3] = fma2(ad[i], b1.y, acc[i][3]);
            }
        }
        __syncthreads();
    }
    #pragma unroll
    for (int i = 0; i < 4; i++) {
        int row = rowBase + m0 + i;
        if (row >= NV) continue;
        float s = g_ns[row];
        float4 o0 = make_float4(flo(acc[i][0]) * s, fhi(acc[i][0]) * s,
                                flo(acc[i][1]) * s, fhi(acc[i][1]) * s);
        float4 o1 = make_float4(flo(acc[i][2]) * s, fhi(acc[i][2]) * s,
                                flo(acc[i][3]) * s, fhi(acc[i][3]) * s);
        *reinterpret_cast<float4*>(g_hs + (size_t)row * HID + c0) = o0;
        *reinterpret_cast<float4*>(g_hs + (size_t)row * HID + c0 + 4) = o1;
    }
}

// ---------------- fused layer GEMM (R6 + padded A) ---------------------------
__global__ void __launch_bounds__(128)
k_gemm_fused(const float* __restrict__ bias,
             const float* __restrict__ W,
             const float* __restrict__ Wo,
             int hasW, int firstY) {
    __shared__ float As[TM][PADA];
    __shared__ float Bw[64][64];
    __shared__ float Bo[64][64];
    int t = threadIdx.x;
    int tx = t & 15, ty = t >> 4;
    int c0 = tx * 4, m0 = ty * 4;
    int rowBase = blockIdx.x * TM;

    #pragma unroll
    for (int i = 0; i < 4; i++) {
        int f4 = t + i * 128;
        int m = f4 >> 4, k4 = (f4 & 15) * 4;
        int row = rowBase + m;
        float4 v = *reinterpret_cast<const float4*>(g_agg + (size_t)row * HID + k4);
        float nd = g_nd[row];
        float4 bb = *reinterpret_cast<const float4*>(bias + k4);
        float4 a;
        a.x = fmaxf(v.x * nd + bb.x, 0.f);
        a.y = fmaxf(v.y * nd + bb.y, 0.f);
        a.z = fmaxf(v.z * nd + bb.z, 0.f);
        a.w = fmaxf(v.w * nd + bb.w, 0.f);
        *reinterpret_cast<float4*>(&As[m][k4]) = a;
    }
    if (hasW) {
        #pragma unroll
        for (int i = 0; i < 8; i++) {
            int f4 = t + i * 128;
            int k = f4 >> 4, c4 = (f4 & 15) * 4;
            *reinterpret_cast<float4*>(&Bw[k][c4]) =
                *reinterpret_cast<const float4*>(W + (size_t)k * HID + c4);
        }
    }
    #pragma unroll
    for (int i = 0; i < 8; i++) {
        int f4 = t + i * 128;
        int k = f4 >> 4, c4 = (f4 & 15) * 4;
        *reinterpret_cast<float4*>(&Bo[k][c4]) =
            *reinterpret_cast<const float4*>(Wo + (size_t)k * HID + c4);
    }
    __syncthreads();

    ull accw2[4][2];
    ull acco2[4][2];
    #pragma unroll
    for (int i = 0; i < 4; i++) {
        accw2[i][0] = 0ull; accw2[i][1] = 0ull;
        acco2[i][0] = 0ull; acco2[i][1] = 0ull;
    }

    if (hasW) {
        #pragma unroll 16
        for (int k = 0; k < 64; k++) {
            ull ad[4];
            #pragma unroll
            for (int i = 0; i < 4; i++) ad[i] = dup2(As[m0 + i][k]);
            ulonglong2 bw = *reinterpret_cast<const ulonglong2*>(&Bw[k][c0]);
            ulonglong2 bo = *reinterpret_cast<const ulonglong2*>(&Bo[k][c0]);
            #pragma unroll
            for (int i = 0; i < 4; i++) {
                accw2[i][0] = fma2(ad[i], bw.x, accw2[i][0]);
                accw2[i][1] = fma2(ad[i], bw.y, accw2[i][1]);
                acco2[i][0] = fma2(ad[i], bo.x, acco2[i][0]);
                acco2[i][1] = fma2(ad[i], bo.y, acco2[i][1]);
            }
        }
    } else {
        #pragma unroll 16
        for (int k = 0; k < 64; k++) {
            ull ad[4];
            #pragma unroll
            for (int i = 0; i < 4; i++) ad[i] = dup2(As[m0 + i][k]);
            ulonglong2 bo = *reinterpret_cast<const ulonglong2*>(&Bo[k][c0]);
            #pragma unroll
            for (int i = 0; i < 4; i++) {
                acco2[i][0] = fma2(ad[i], bo.x, acco2[i][0]);
                acco2[i][1] = fma2(ad[i], bo.y, acco2[i][1]);
            }
        }
    }

    #pragma unroll
    for (int i = 0; i < 4; i++) {
        int row = rowBase + m0 + i;
        if (hasW) {
            float s = g_ns[row];
            float4 o = make_float4(flo(accw2[i][0]) * s, fhi(accw2[i][0]) * s,
                                   flo(accw2[i][1]) * s, fhi(accw2[i][1]) * s);
            *reinterpret_cast<float4*>(g_hs + (size_t)row * HID + c0) = o;
        }
        float4* yp = reinterpret_cast<float4*>(g_y + (size_t)row * HID + c0);
        float4 yn = make_float4(flo(acco2[i][0]), fhi(acco2[i][0]),
                                flo(acco2[i][1]), fhi(acco2[i][1]));
        if (firstY) {
            *yp = yn;
        } else {
            float4 yv = *yp;
            yv.x += yn.x; yv.y += yn.y; yv.z += yn.z; yv.w += yn.w;
            *yp = yv;
        }
    }
}

// ---------------- launch ------------------------------------------------------
extern "C" void kernel_launch(void* const* d_in, const int* in_sizes, int n_in,
                              void* d_out, int out_size) {
    const float* feats = (const float*)d_in[0];
    const int*   src   = (const int*)d_in[1];
    const int*   dst   = (const int*)d_in[2];
    const float* W[5];
    const float* B[5];
    for (int i = 0; i < 5; i++) {
        W[i] = (const float*)d_in[3 + 2 * i];
        B[i] = (const float*)d_in[4 + 2 * i];
    }
    const float* Wout = (const float*)d_in[13];
    const float* bout = (const float*)d_in[14];
    float* out = (float*)d_out;

    const int TPB = 256;
    const int NB_V = (NV + TPB - 1) / TPB;      // 391
    const int NB_E = (NE + TPB - 1) / TPB;      // 6250
    const int NB_G = (NV * 32 + TPB - 1) / TPB; // 12500 (warp per node)

    // prologue (gemm0 kept in the ncu-sampled 4th slot)
    k_zero0<<<NB_V, TPB>>>();
    k_deg<<<NB_E, TPB>>>(src, dst);
    k_norm<<<NB_V, TPB>>>();
    k_gemm0<<<(NV + 63) / 64, 128>>>(feats, W[0]);

    // CSR build (independent of gemm0)
    k_scan1<<<NB_V, 256>>>();
    k_scan2<<<1, 512>>>();
    k_scan3<<<NB_V, TPB>>>();
    k_fill<<<NB_E, TPB>>>(src, dst);

    // 5 message-passing layers
    for (int l = 0; l < 5; l++) {
        k_gather_hs<<<NB_G, TPB>>>();
        int hasW = (l < 4) ? 1 : 0;
        k_gemm_fused<<<NV / TM, 128>>>(B[l],
                                       hasW ? W[l + 1] : W[0],
                                       Wout + (size_t)l * HID * 64,
                                       hasW, l == 0 ? 1 : 0);
    }

    // final aggregation straight into out (+bout)
    k_gather_out<<<NB_G, TPB>>>(out, bout);
}

// round 8
// speedup vs baseline: 1.0362x; 1.0362x over previous
#include <cuda_runtime.h>

#define NV 100000
#define NE 1600000
#define HID 64
#define FIN 256
#define TM 32
#define PADA 68
#define NBLK_SCAN 391   // ceil(NV/256)

typedef unsigned long long ull;

// ---------------- scratch (static device globals) ---------------------------
__device__ float g_ns[NV];
__device__ float g_nd[NV];
__device__ int   g_odeg[NV];
__device__ int   g_indeg[NV];
__device__ int   g_rowptr[NV + 1];
__device__ int   g_cur[NV];
__device__ int   g_bsum[512];
__device__ int   g_boff[512];
__device__ int   g_esrc[NE];                  // src ids grouped by dst (CSR)
__device__ float g_hs[(size_t)NV * HID];      // per-layer message table
__device__ float g_agg[(size_t)NV * HID];     // gather destination
__device__ float g_y[(size_t)NV * HID];       // accumulated out @ Wout

// ---------------- f32x2 helpers ----------------------------------------------
__device__ __forceinline__ ull fma2(ull a, ull b, ull c) {
    ull d;
    asm("fma.rn.f32x2 %0, %1, %2, %3;" : "=l"(d) : "l"(a), "l"(b), "l"(c));
    return d;
}
__device__ __forceinline__ ull dup2(float x) {
    ull d;
    asm("mov.b64 %0, {%1, %1};" : "=l"(d) : "f"(x));
    return d;
}
__device__ __forceinline__ float flo(ull u) { return __uint_as_float((unsigned)u); }
__device__ __forceinline__ float fhi(ull u) { return __uint_as_float((unsigned)(u >> 32)); }

// ---------------- degree / CSR build ----------------------------------------
__global__ void k_zero0() {
    int i = blockIdx.x * blockDim.x + threadIdx.x;
    if (i < NV) { g_odeg[i] = 0; g_indeg[i] = 0; }
}

__global__ void k_deg(const int* __restrict__ src, const int* __restrict__ dst) {
    int e = blockIdx.x * blockDim.x + threadIdx.x;
    if (e < NE) {
        atomicAdd(&g_odeg[src[e]], 1);
        atomicAdd(&g_indeg[dst[e]], 1);
    }
}

__global__ void k_norm() {
    int i = blockIdx.x * blockDim.x + threadIdx.x;
    if (i < NV) {
        g_ns[i] = rsqrtf(fmaxf((float)g_odeg[i], 1.f));
        g_nd[i] = rsqrtf(fmaxf((float)g_indeg[i], 1.f));
    }
}

__global__ void __launch_bounds__(256) k_scan1() {
    __shared__ int sm[256];
    int t = threadIdx.x;
    int i = blockIdx.x * 256 + t;
    int v = (i < NV) ? g_indeg[i] : 0;
    sm[t] = v;
    __syncthreads();
    #pragma unroll
    for (int ofs = 1; ofs < 256; ofs <<= 1) {
        int add = (t >= ofs) ? sm[t - ofs] : 0;
        __syncthreads();
        sm[t] += add;
        __syncthreads();
    }
    if (i < NV) g_rowptr[i] = sm[t] - v;
    if (t == 255) g_bsum[blockIdx.x] = sm[255];
}

__global__ void __launch_bounds__(512) k_scan2() {
    __shared__ int sm[512];
    int t = threadIdx.x;
    int v = (t < NBLK_SCAN) ? g_bsum[t] : 0;
    sm[t] = v;
    __syncthreads();
    #pragma unroll
    for (int ofs = 1; ofs < 512; ofs <<= 1) {
        int add = (t >= ofs) ? sm[t - ofs] : 0;
        __syncthreads();
        sm[t] += add;
        __syncthreads();
    }
    g_boff[t] = sm[t] - v;
}

__global__ void k_scan3() {
    int i = blockIdx.x * blockDim.x + threadIdx.x;
    if (i < NV) {
        int r = g_rowptr[i] + g_boff[i >> 8];
        g_rowptr[i] = r;
        g_cur[i] = r;
    }
    if (i == 0) g_rowptr[NV] = NE;
}

__global__ void k_fill(const int* __restrict__ src, const int* __restrict__ dst) {
    int e = blockIdx.x * blockDim.x + threadIdx.x;
    if (e < NE) {
        int pos = atomicAdd(&g_cur[dst[e]], 1);
        g_esrc[pos] = src[e];
    }
}

// ---------------- CSR gather (R4 structure) -----------------------------------
__global__ void __launch_bounds__(256)
k_gather_hs() {
    int w = (blockIdx.x * 256 + threadIdx.x) >> 5;
    int lane = threadIdx.x & 31;
    if (w >= NV) return;
    int beg = g_rowptr[w], end = g_rowptr[w + 1];
    const float2* tb = reinterpret_cast<const float2*>(g_hs);
    float2 acc = make_float2(0.f, 0.f);
    int e = beg;
    for (; e + 4 <= end; e += 4) {
        int s0 = g_esrc[e], s1 = g_esrc[e + 1], s2 = g_esrc[e + 2], s3 = g_esrc[e + 3];
        float2 v0 = tb[(size_t)s0 * 32 + lane];
        float2 v1 = tb[(size_t)s1 * 32 + lane];
        float2 v2 = tb[(size_t)s2 * 32 + lane];
        float2 v3 = tb[(size_t)s3 * 32 + lane];
        acc.x += (v0.x + v1.x) + (v2.x + v3.x);
        acc.y += (v0.y + v1.y) + (v2.y + v3.y);
    }
    for (; e < end; e++) {
        int s = g_esrc[e];
        float2 v = tb[(size_t)s * 32 + lane];
        acc.x += v.x; acc.y += v.y;
    }
    reinterpret_cast<float2*>(g_agg)[(size_t)w * 32 + lane] = acc;
}

__global__ void __launch_bounds__(256)
k_gather_out(float* __restrict__ out, const float* __restrict__ bout) {
    int w = (blockIdx.x * 256 + threadIdx.x) >> 5;
    int lane = threadIdx.x & 31;
    if (w >= NV) return;
    int beg = g_rowptr[w], end = g_rowptr[w + 1];
    const float2* tb = reinterpret_cast<const float2*>(g_y);
    float2 acc = reinterpret_cast<const float2*>(bout)[lane];
    int e = beg;
    for (; e + 4 <= end; e += 4) {
        int s0 = g_esrc[e], s1 = g_esrc[e + 1], s2 = g_esrc[e + 2], s3 = g_esrc[e + 3];
        float2 v0 = tb[(size_t)s0 * 32 + lane];
        float2 v1 = tb[(size_t)s1 * 32 + lane];
        float2 v2 = tb[(size_t)s2 * 32 + lane];
        float2 v3 = tb[(size_t)s3 * 32 + lane];
        acc.x += (v0.x + v1.x) + (v2.x + v3.x);
        acc.y += (v0.y + v1.y) + (v2.y + v3.y);
    }
    for (; e < end; e++) {
        int s = g_esrc[e];
        float2 v = tb[(size_t)s * 32 + lane];
        acc.x += v.x; acc.y += v.y;
    }
    reinterpret_cast<float2*>(out)[(size_t)w * 32 + lane] = acc;
}

// ---------------- GEMM 0: hs = ns * (feats @ W0), K=256 ---------------------
// R6 layout (32x64 tile, 128 thr, 4x4 micro, f32x2 pairs along N)
// + PADA row padding (A bank-conflict-free) + LDS.64 A-pair loads.
__global__ void __launch_bounds__(128)
k_gemm0(const float* __restrict__ feats, const float* __restrict__ W0) {
    __shared__ float As[TM][PADA];
    __shared__ float Bs[64][64];
    int t = threadIdx.x;
    int tx = t & 15, ty = t >> 4;
    int c0 = tx * 4, m0 = ty * 4;
    int rowBase = blockIdx.x * TM;

    ull acc2[4][2];
    #pragma unroll
    for (int i = 0; i < 4; i++) { acc2[i][0] = 0ull; acc2[i][1] = 0ull; }

    for (int kb = 0; kb < FIN; kb += 64) {
        #pragma unroll
        for (int i = 0; i < 4; i++) {              // A tile: 32x64
            int f4 = t + i * 128;
            int m = f4 >> 4, k4 = (f4 & 15) * 4;
            *reinterpret_cast<float4*>(&As[m][k4]) =
                *reinterpret_cast<const float4*>(feats + (size_t)(rowBase + m) * FIN + kb + k4);
        }
        #pragma unroll
        for (int i = 0; i < 8; i++) {              // B tile: 64x64
            int f4 = t + i * 128;
            int k = f4 >> 4, c4 = (f4 & 15) * 4;
            *reinterpret_cast<float4*>(&Bs[k][c4]) =
                *reinterpret_cast<const float4*>(W0 + (size_t)(kb + k) * HID + c4);
        }
        __syncthreads();
        #pragma unroll 8
        for (int k = 0; k < 64; k += 2) {
            ull ap[4];
            #pragma unroll
            for (int i = 0; i < 4; i++)
                ap[i] = *reinterpret_cast<const ull*>(&As[m0 + i][k]);
            ulonglong2 b0 = *reinterpret_cast<const ulonglong2*>(&Bs[k][c0]);
            ulonglong2 b1 = *reinterpret_cast<const ulonglong2*>(&Bs[k + 1][c0]);
            #pragma unroll
            for (int i = 0; i < 4; i++) {
                ull alo = dup2(flo(ap[i]));
                ull ahi = dup2(fhi(ap[i]));
                acc2[i][0] = fma2(alo, b0.x, acc2[i][0]);
                acc2[i][1] = fma2(alo, b0.y, acc2[i][1]);
                acc2[i][0] = fma2(ahi, b1.x, acc2[i][0]);
                acc2[i][1] = fma2(ahi, b1.y, acc2[i][1]);
            }
        }
        __syncthreads();
    }
    #pragma unroll
    for (int i = 0; i < 4; i++) {
        int row = rowBase + m0 + i;
        float s = g_ns[row];
        float4 o = make_float4(flo(acc2[i][0]) * s, fhi(acc2[i][0]) * s,
                               flo(acc2[i][1]) * s, fhi(acc2[i][1]) * s);
        *reinterpret_cast<float4*>(g_hs + (size_t)row * HID + c0) = o;
    }
}

// ---------------- fused layer GEMM (R6 + PADA + LDS.64 A pairs) --------------
// A = relu(agg * nd + bias)   (SMEM only)
// if hasW:   hs = ns * (A @ W)
// firstY=1:  y  = A @ Wo       else  y += A @ Wo
__global__ void __launch_bounds__(128)
k_gemm_fused(const float* __restrict__ bias,
             const float* __restrict__ W,
             const float* __restrict__ Wo,
             int hasW, int firstY) {
    __shared__ float As[TM][PADA];
    __shared__ float Bw[64][64];
    __shared__ float Bo[64][64];
    int t = threadIdx.x;
    int tx = t & 15, ty = t >> 4;
    int c0 = tx * 4, m0 = ty * 4;
    int rowBase = blockIdx.x * TM;

    #pragma unroll
    for (int i = 0; i < 4; i++) {
        int f4 = t + i * 128;
        int m = f4 >> 4, k4 = (f4 & 15) * 4;
        int row = rowBase + m;
        float4 v = *reinterpret_cast<const float4*>(g_agg + (size_t)row * HID + k4);
        float nd = g_nd[row];
        float4 bb = *reinterpret_cast<const float4*>(bias + k4);
        float4 a;
        a.x = fmaxf(v.x * nd + bb.x, 0.f);
        a.y = fmaxf(v.y * nd + bb.y, 0.f);
        a.z = fmaxf(v.z * nd + bb.z, 0.f);
        a.w = fmaxf(v.w * nd + bb.w, 0.f);
        *reinterpret_cast<float4*>(&As[m][k4]) = a;
    }
    if (hasW) {
        #pragma unroll
        for (int i = 0; i < 8; i++) {
            int f4 = t + i * 128;
            int k = f4 >> 4, c4 = (f4 & 15) * 4;
            *reinterpret_cast<float4*>(&Bw[k][c4]) =
                *reinterpret_cast<const float4*>(W + (size_t)k * HID + c4);
        }
    }
    #pragma unroll
    for (int i = 0; i < 8; i++) {
        int f4 = t + i * 128;
        int k = f4 >> 4, c4 = (f4 & 15) * 4;
        *reinterpret_cast<float4*>(&Bo[k][c4]) =
            *reinterpret_cast<const float4*>(Wo + (size_t)k * HID + c4);
    }
    __syncthreads();

    ull accw2[4][2];
    ull acco2[4][2];
    #pragma unroll
    for (int i = 0; i < 4; i++) {
        accw2[i][0] = 0ull; accw2[i][1] = 0ull;
        acco2[i][0] = 0ull; acco2[i][1] = 0ull;
    }

    if (hasW) {
        #pragma unroll 8
        for (int k = 0; k < 64; k += 2) {
            ull ap[4];
            #pragma unroll
            for (int i = 0; i < 4; i++)
                ap[i] = *reinterpret_cast<const ull*>(&As[m0 + i][k]);
            ulonglong2 bw0 = *reinterpret_cast<const ulonglong2*>(&Bw[k][c0]);
            ulonglong2 bw1 = *reinterpret_cast<const ulonglong2*>(&Bw[k + 1][c0]);
            ulonglong2 bo0 = *reinterpret_cast<const ulonglong2*>(&Bo[k][c0]);
            ulonglong2 bo1 = *reinterpret_cast<const ulonglong2*>(&Bo[k + 1][c0]);
            #pragma unroll
            for (int i = 0; i < 4; i++) {
                ull alo = dup2(flo(ap[i]));
                ull ahi = dup2(fhi(ap[i]));
                accw2[i][0] = fma2(alo, bw0.x, accw2[i][0]);
                accw2[i][1] = fma2(alo, bw0.y, accw2[i][1]);
                acco2[i][0] = fma2(alo, bo0.x, acco2[i][0]);
                acco2[i][1] = fma2(alo, bo0.y, acco2[i][1]);
                accw2[i][0] = fma2(ahi, bw1.x, accw2[i][0]);
                accw2[i][1] = fma2(ahi, bw1.y, accw2[i][1]);
                acco2[i][0] = fma2(ahi, bo1.x, acco2[i][0]);
                acco2[i][1] = fma2(ahi, bo1.y, acco2[i][1]);
            }
        }
    } else {
        #pragma unroll 8
        for (int k = 0; k < 64; k += 2) {
            ull ap[4];
            #pragma unroll
            for (int i = 0; i < 4; i++)
                ap[i] = *reinterpret_cast<const ull*>(&As[m0 + i][k]);
            ulonglong2 bo0 = *reinterpret_cast<const ulonglong2*>(&Bo[k][c0]);
            ulonglong2 bo1 = *reinterpret_cast<const ulonglong2*>(&Bo[k + 1][c0]);
            #pragma unroll
            for (int i = 0; i < 4; i++) {
                ull alo = dup2(flo(ap[i]));
                ull ahi = dup2(fhi(ap[i]));
                acco2[i][0] = fma2(alo, bo0.x, acco2[i][0]);
                acco2[i][1] = fma2(alo, bo0.y, acco2[i][1]);
                acco2[i][0] = fma2(ahi, bo1.x, acco2[i][0]);
                acco2[i][1] = fma2(ahi, bo1.y, acco2[i][1]);
            }
        }
    }

    #pragma unroll
    for (int i = 0; i < 4; i++) {
        int row = rowBase + m0 + i;
        if (hasW) {
            float s = g_ns[row];
            float4 o = make_float4(flo(accw2[i][0]) * s, fhi(accw2[i][0]) * s,
                                   flo(accw2[i][1]) * s, fhi(accw2[i][1]) * s);
            *reinterpret_cast<float4*>(g_hs + (size_t)row * HID + c0) = o;
        }
        float4* yp = reinterpret_cast<float4*>(g_y + (size_t)row * HID + c0);
        float4 yn = make_float4(flo(acco2[i][0]), fhi(acco2[i][0]),
                                flo(acco2[i][1]), fhi(acco2[i][1]));
        if (firstY) {
            *yp = yn;
        } else {
            float4 yv = *yp;
            yv.x += yn.x; yv.y += yn.y; yv.z += yn.z; yv.w += yn.w;
            *yp = yv;
        }
    }
}

// ---------------- launch ------------------------------------------------------
extern "C" void kernel_launch(void* const* d_in, const int* in_sizes, int n_in,
                              void* d_out, int out_size) {
    const float* feats = (const float*)d_in[0];
    const int*   src   = (const int*)d_in[1];
    const int*   dst   = (const int*)d_in[2];
    const float* W[5];
    const float* B[5];
    for (int i = 0; i < 5; i++) {
        W[i] = (const float*)d_in[3 + 2 * i];
        B[i] = (const float*)d_in[4 + 2 * i];
    }
    const float* Wout = (const float*)d_in[13];
    const float* bout = (const float*)d_in[14];
    float* out = (float*)d_out;

    const int TPB = 256;
    const int NB_V = (NV + TPB - 1) / TPB;      // 391
    const int NB_E = (NE + TPB - 1) / TPB;      // 6250
    const int NB_G = (NV * 32 + TPB - 1) / TPB; // 12500 (warp per node)

    // prologue (gemm0 kept in the ncu-sampled 4th slot)
    k_zero0<<<NB_V, TPB>>>();
    k_deg<<<NB_E, TPB>>>(src, dst);
    k_norm<<<NB_V, TPB>>>();
    k_gemm0<<<NV / TM, 128>>>(feats, W[0]);

    // CSR build (independent of gemm0)
    k_scan1<<<NB_V, 256>>>();
    k_scan2<<<1, 512>>>();
    k_scan3<<<NB_V, TPB>>>();
    k_fill<<<NB_E, TPB>>>(src, dst);

    // 5 message-passing layers
    for (int l = 0; l < 5; l++) {
        k_gather_hs<<<NB_G, TPB>>>();
        int hasW = (l < 4) ? 1 : 0;
        k_gemm_fused<<<NV / TM, 128>>>(B[l],
                                       hasW ? W[l + 1] : W[0],
                                       Wout + (size_t)l * HID * 64,
                                       hasW, l == 0 ? 1 : 0);
    }

    // final aggregation straight into out (+bout)
    k_gather_out<<<NB_G, TPB>>>(out, bout);
}

// round 10
// speedup vs baseline: 1.0557x; 1.0188x over previous
#include <cuda_runtime.h>
#include <cuda_fp16.h>

#define NV 100000
#define NE 1600000
#define HID 64
#define FIN 256
#define TM 32
#define PADA 68
#define NBLK_SCAN 391   // ceil(NV/256)

typedef unsigned long long ull;

// ---------------- scratch (static device globals) ---------------------------
__device__ float   g_ns[NV];
__device__ float   g_nd[NV];
__device__ int     g_odeg[NV];
__device__ int     g_indeg[NV];
__device__ int     g_rowptr[NV + 1];
__device__ int     g_cur[NV];
__device__ int     g_bsum[512];
__device__ int     g_boff[512];
__device__ int     g_esrc[NE];                   // src ids grouped by dst (CSR)
__device__ __half2 g_hs2[(size_t)NV * 32];       // fp16 message table (64 cols)
__device__ float   g_agg[(size_t)NV * HID];      // gather destination (fp32)
__device__ float   g_y[(size_t)NV * HID];        // accumulated out @ Wout (fp32)

// ---------------- f32x2 helpers ----------------------------------------------
__device__ __forceinline__ ull fma2(ull a, ull b, ull c) {
    ull d;
    asm("fma.rn.f32x2 %0, %1, %2, %3;" : "=l"(d) : "l"(a), "l"(b), "l"(c));
    return d;
}
__device__ __forceinline__ ull dup2(float x) {
    ull d;
    asm("mov.b64 %0, {%1, %1};" : "=l"(d) : "f"(x));
    return d;
}
__device__ __forceinline__ float flo(ull u) { return __uint_as_float((unsigned)u); }
__device__ __forceinline__ float fhi(ull u) { return __uint_as_float((unsigned)(u >> 32)); }

// ---------------- degree / CSR build ----------------------------------------
__global__ void k_zero0() {
    int i = blockIdx.x * blockDim.x + threadIdx.x;
    if (i < NV) { g_odeg[i] = 0; g_indeg[i] = 0; }
}

__global__ void k_deg(const int* __restrict__ src, const int* __restrict__ dst) {
    int e = blockIdx.x * blockDim.x + threadIdx.x;
    if (e < NE) {
        atomicAdd(&g_odeg[src[e]], 1);
        atomicAdd(&g_indeg[dst[e]], 1);
    }
}

__global__ void k_norm() {
    int i = blockIdx.x * blockDim.x + threadIdx.x;
    if (i < NV) {
        g_ns[i] = rsqrtf(fmaxf((float)g_odeg[i], 1.f));
        g_nd[i] = rsqrtf(fmaxf((float)g_indeg[i], 1.f));
    }
}

__global__ void __launch_bounds__(256) k_scan1() {
    __shared__ int sm[256];
    int t = threadIdx.x;
    int i = blockIdx.x * 256 + t;
    int v = (i < NV) ? g_indeg[i] : 0;
    sm[t] = v;
    __syncthreads();
    #pragma unroll
    for (int ofs = 1; ofs < 256; ofs <<= 1) {
        int add = (t >= ofs) ? sm[t - ofs] : 0;
        __syncthreads();
        sm[t] += add;
        __syncthreads();
    }
    if (i < NV) g_rowptr[i] = sm[t] - v;
    if (t == 255) g_bsum[blockIdx.x] = sm[255];
}

__global__ void __launch_bounds__(512) k_scan2() {
    __shared__ int sm[512];
    int t = threadIdx.x;
    int v = (t < NBLK_SCAN) ? g_bsum[t] : 0;
    sm[t] = v;
    __syncthreads();
    #pragma unroll
    for (int ofs = 1; ofs < 512; ofs <<= 1) {
        int add = (t >= ofs) ? sm[t - ofs] : 0;
        __syncthreads();
        sm[t] += add;
        __syncthreads();
    }
    g_boff[t] = sm[t] - v;
}

__global__ void k_scan3() {
    int i = blockIdx.x * blockDim.x + threadIdx.x;
    if (i < NV) {
        int r = g_rowptr[i] + g_boff[i >> 8];
        g_rowptr[i] = r;
        g_cur[i] = r;
    }
    if (i == 0) g_rowptr[NV] = NE;
}

__global__ void k_fill(const int* __restrict__ src, const int* __restrict__ dst) {
    int e = blockIdx.x * blockDim.x + threadIdx.x;
    if (e < NE) {
        int pos = atomicAdd(&g_cur[dst[e]], 1);
        g_esrc[pos] = src[e];
    }
}

// ---------------- CSR gather hs (fp16 table -> fp32 accum) --------------------
__global__ void __launch_bounds__(256)
k_gather_hs() {
    int w = (blockIdx.x * 256 + threadIdx.x) >> 5;
    int lane = threadIdx.x & 31;
    if (w >= NV) return;
    int beg = g_rowptr[w], end = g_rowptr[w + 1];
    float2 acc = make_float2(0.f, 0.f);
    int e = beg;
    for (; e + 4 <= end; e += 4) {
        int s0 = g_esrc[e], s1 = g_esrc[e + 1], s2 = g_esrc[e + 2], s3 = g_esrc[e + 3];
        float2 v0 = __half22float2(g_hs2[(size_t)s0 * 32 + lane]);
        float2 v1 = __half22float2(g_hs2[(size_t)s1 * 32 + lane]);
        float2 v2 = __half22float2(g_hs2[(size_t)s2 * 32 + lane]);
        float2 v3 = __half22float2(g_hs2[(size_t)s3 * 32 + lane]);
        acc.x += (v0.x + v1.x) + (v2.x + v3.x);
        acc.y += (v0.y + v1.y) + (v2.y + v3.y);
    }
    for (; e < end; e++) {
        int s = g_esrc[e];
        float2 v = __half22float2(g_hs2[(size_t)s * 32 + lane]);
        acc.x += v.x; acc.y += v.y;
    }
    reinterpret_cast<float2*>(g_agg)[(size_t)w * 32 + lane] = acc;
}

// final: out[n] = bout + sum g_y[esrc[e]]   (fp32 table)
__global__ void __launch_bounds__(256)
k_gather_out(float* __restrict__ out, const float* __restrict__ bout) {
    int w = (blockIdx.x * 256 + threadIdx.x) >> 5;
    int lane = threadIdx.x & 31;
    if (w >= NV) return;
    int beg = g_rowptr[w], end = g_rowptr[w + 1];
    const float2* tb = reinterpret_cast<const float2*>(g_y);
    float2 acc = reinterpret_cast<const float2*>(bout)[lane];
    int e = beg;
    for (; e + 4 <= end; e += 4) {
        int s0 = g_esrc[e], s1 = g_esrc[e + 1], s2 = g_esrc[e + 2], s3 = g_esrc[e + 3];
        float2 v0 = tb[(size_t)s0 * 32 + lane];
        float2 v1 = tb[(size_t)s1 * 32 + lane];
        float2 v2 = tb[(size_t)s2 * 32 + lane];
        float2 v3 = tb[(size_t)s3 * 32 + lane];
        acc.x += (v0.x + v1.x) + (v2.x + v3.x);
        acc.y += (v0.y + v1.y) + (v2.y + v3.y);
    }
    for (; e < end; e++) {
        int s = g_esrc[e];
        float2 v = tb[(size_t)s * 32 + lane];
        acc.x += v.x; acc.y += v.y;
    }
    reinterpret_cast<float2*>(out)[(size_t)w * 32 + lane] = acc;
}

// ---------------- GEMM 0: hs = ns * (feats @ W0), K=256 (R8 kernel) ----------
__global__ void __launch_bounds__(128)
k_gemm0(const float* __restrict__ feats, const float* __restrict__ W0) {
    __shared__ float As[TM][PADA];
    __shared__ float Bs[64][64];
    int t = threadIdx.x;
    int tx = t & 15, ty = t >> 4;
    int c0 = tx * 4, m0 = ty * 4;
    int rowBase = blockIdx.x * TM;

    ull acc2[4][2];
    #pragma unroll
    for (int i = 0; i < 4; i++) { acc2[i][0] = 0ull; acc2[i][1] = 0ull; }

    for (int kb = 0; kb < FIN; kb += 64) {
        #pragma unroll
        for (int i = 0; i < 4; i++) {              // A tile: 32x64
            int f4 = t + i * 128;
            int m = f4 >> 4, k4 = (f4 & 15) * 4;
            *reinterpret_cast<float4*>(&As[m][k4]) =
                *reinterpret_cast<const float4*>(feats + (size_t)(rowBase + m) * FIN + kb + k4);
        }
        #pragma unroll
        for (int i = 0; i < 8; i++) {              // B tile: 64x64
            int f4 = t + i * 128;
            int k = f4 >> 4, c4 = (f4 & 15) * 4;
            *reinterpret_cast<float4*>(&Bs[k][c4]) =
                *reinterpret_cast<const float4*>(W0 + (size_t)(kb + k) * HID + c4);
        }
        __syncthreads();
        #pragma unroll 8
        for (int k = 0; k < 64; k += 2) {
            ull ap[4];
            #pragma unroll
            for (int i = 0; i < 4; i++)
                ap[i] = *reinterpret_cast<const ull*>(&As[m0 + i][k]);
            ulonglong2 b0 = *reinterpret_cast<const ulonglong2*>(&Bs[k][c0]);
            ulonglong2 b1 = *reinterpret_cast<const ulonglong2*>(&Bs[k + 1][c0]);
            #pragma unroll
            for (int i = 0; i < 4; i++) {
                ull alo = dup2(flo(ap[i]));
                ull ahi = dup2(fhi(ap[i]));
                acc2[i][0] = fma2(alo, b0.x, acc2[i][0]);
                acc2[i][1] = fma2(alo, b0.y, acc2[i][1]);
                acc2[i][0] = fma2(ahi, b1.x, acc2[i][0]);
                acc2[i][1] = fma2(ahi, b1.y, acc2[i][1]);
            }
        }
        __syncthreads();
    }
    #pragma unroll
    for (int i = 0; i < 4; i++) {
        int row = rowBase + m0 + i;
        float s = g_ns[row];
        __half2* hp = &g_hs2[(size_t)row * 32 + (c0 >> 1)];
        hp[0] = __floats2half2_rn(flo(acc2[i][0]) * s, fhi(acc2[i][0]) * s);
        hp[1] = __floats2half2_rn(flo(acc2[i][1]) * s, fhi(acc2[i][1]) * s);
    }
}

// ---------------- fused layer GEMM (R8 + fp16 hs epilogue) -------------------
__global__ void __launch_bounds__(128)
k_gemm_fused(const float* __restrict__ bias,
             const float* __restrict__ W,
             const float* __restrict__ Wo,
             int hasW, int firstY) {
    __shared__ float As[TM][PADA];
    __shared__ float Bw[64][64];
    __shared__ float Bo[64][64];
    int t = threadIdx.x;
    int tx = t & 15, ty = t >> 4;
    int c0 = tx * 4, m0 = ty * 4;
    int rowBase = blockIdx.x * TM;

    #pragma unroll
    for (int i = 0; i < 4; i++) {
        int f4 = t + i * 128;
        int m = f4 >> 4, k4 = (f4 & 15) * 4;
        int row = rowBase + m;
        float4 v = *reinterpret_cast<const float4*>(g_agg + (size_t)row * HID + k4);
        float nd = g_nd[row];
        float4 bb = *reinterpret_cast<const float4*>(bias + k4);
        float4 a;
        a.x = fmaxf(v.x * nd + bb.x, 0.f);
        a.y = fmaxf(v.y * nd + bb.y, 0.f);
        a.z = fmaxf(v.z * nd + bb.z, 0.f);
        a.w = fmaxf(v.w * nd + bb.w, 0.f);
        *reinterpret_cast<float4*>(&As[m][k4]) = a;
    }
    if (hasW) {
        #pragma unroll
        for (int i = 0; i < 8; i++) {
            int f4 = t + i * 128;
            int k = f4 >> 4, c4 = (f4 & 15) * 4;
            *reinterpret_cast<float4*>(&Bw[k][c4]) =
                *reinterpret_cast<const float4*>(W + (size_t)k * HID + c4);
        }
    }
    #pragma unroll
    for (int i = 0; i < 8; i++) {
        int f4 = t + i * 128;
        int k = f4 >> 4, c4 = (f4 & 15) * 4;
        *reinterpret_cast<float4*>(&Bo[k][c4]) =
            *reinterpret_cast<const float4*>(Wo + (size_t)k * HID + c4);
    }
    __syncthreads();

    ull accw2[4][2];
    ull acco2[4][2];
    #pragma unroll
    for (int i = 0; i < 4; i++) {
        accw2[i][0] = 0ull; accw2[i][1] = 0ull;
        acco2[i][0] = 0ull; acco2[i][1] = 0ull;
    }

    if (hasW) {
        #pragma unroll 8
        for (int k = 0; k < 64; k += 2) {
            ull ap[4];
            #pragma unroll
            for (int i = 0; i < 4; i++)
                ap[i] = *reinterpret_cast<const ull*>(&As[m0 + i][k]);
            ulonglong2 bw0 = *reinterpret_cast<const ulonglong2*>(&Bw[k][c0]);
            ulonglong2 bw1 = *reinterpret_cast<const ulonglong2*>(&Bw[k + 1][c0]);
            ulonglong2 bo0 = *reinterpret_cast<const ulonglong2*>(&Bo[k][c0]);
            ulonglong2 bo1 = *reinterpret_cast<const ulonglong2*>(&Bo[k + 1][c0]);
            #pragma unroll
            for (int i = 0; i < 4; i++) {
                ull alo = dup2(flo(ap[i]));
                ull ahi = dup2(fhi(ap[i]));
                accw2[i][0] = fma2(alo, bw0.x, accw2[i][0]);
                accw2[i][1] = fma2(alo, bw0.y, accw2[i][1]);
                acco2[i][0] = fma2(alo, bo0.x, acco2[i][0]);
                acco2[i][1] = fma2(alo, bo0.y, acco2[i][1]);
                accw2[i][0] = fma2(ahi, bw1.x, accw2[i][0]);
                accw2[i][1] = fma2(ahi, bw1.y, accw2[i][1]);
                acco2[i][0] = fma2(ahi, bo1.x, acco2[i][0]);
                acco2[i][1] = fma2(ahi, bo1.y, acco2[i][1]);
            }
        }
    } else {
        #pragma unroll 8
        for (int k = 0; k < 64; k += 2) {
            ull ap[4];
            #pragma unroll
            for (int i = 0; i < 4; i++)
                ap[i] = *reinterpret_cast<const ull*>(&As[m0 + i][k]);
            ulonglong2 bo0 = *reinterpret_cast<const ulonglong2*>(&Bo[k][c0]);
            ulonglong2 bo1 = *reinterpret_cast<const ulonglong2*>(&Bo[k + 1][c0]);
            #pragma unroll
            for (int i = 0; i < 4; i++) {
                ull alo = dup2(flo(ap[i]));
                ull ahi = dup2(fhi(ap[i]));
                acco2[i][0] = fma2(alo, bo0.x, acco2[i][0]);
                acco2[i][1] = fma2(alo, bo0.y, acco2[i][1]);
                acco2[i][0] = fma2(ahi, bo1.x, acco2[i][0]);
                acco2[i][1] = fma2(ahi, bo1.y, acco2[i][1]);
            }
        }
    }

    #pragma unroll
    for (int i = 0; i < 4; i++) {
        int row = rowBase + m0 + i;
        if (hasW) {
            float s = g_ns[row];
            __half2* hp = &g_hs2[(size_t)row * 32 + (c0 >> 1)];
            hp[0] = __floats2half2_rn(flo(accw2[i][0]) * s, fhi(accw2[i][0]) * s);
            hp[1] = __floats2half2_rn(flo(accw2[i][1]) * s, fhi(accw2[i][1]) * s);
        }
        float4* yp = reinterpret_cast<float4*>(g_y + (size_t)row * HID + c0);
        float4 yn = make_float4(flo(acco2[i][0]), fhi(acco2[i][0]),
                                flo(acco2[i][1]), fhi(acco2[i][1]));
        if (firstY) {
            *yp = yn;
        } else {
            float4 yv = *yp;
            yv.x += yn.x; yv.y += yn.y; yv.z += yn.z; yv.w += yn.w;
            *yp = yv;
        }
    }
}

// ---------------- launch ------------------------------------------------------
extern "C" void kernel_launch(void* const* d_in, const int* in_sizes, int n_in,
                              void* d_out, int out_size) {
    const float* feats = (const float*)d_in[0];
    const int*   src   = (const int*)d_in[1];
    const int*   dst   = (const int*)d_in[2];
    const float* W[5];
    const float* B[5];
    for (int i = 0; i < 5; i++) {
        W[i] = (const float*)d_in[3 + 2 * i];
        B[i] = (const float*)d_in[4 + 2 * i];
    }
    const float* Wout = (const float*)d_in[13];
    const float* bout = (const float*)d_in[14];
    float* out = (float*)d_out;

    const int TPB = 256;
    const int NB_V = (NV + TPB - 1) / TPB;      // 391
    const int NB_E = (NE + TPB - 1) / TPB;      // 6250
    const int NB_G = (NV * 32 + TPB - 1) / TPB; // 12500 (warp per node)

    // prologue (gemm0 kept in the ncu-sampled 4th slot)
    k_zero0<<<NB_V, TPB>>>();
    k_deg<<<NB_E, TPB>>>(src, dst);
    k_norm<<<NB_V, TPB>>>();
    k_gemm0<<<NV / TM, 128>>>(feats, W[0]);

    // CSR build (independent of gemm0)
    k_scan1<<<NB_V, 256>>>();
    k_scan2<<<1, 512>>>();
    k_scan3<<<NB_V, TPB>>>();
    k_fill<<<NB_E, TPB>>>(src, dst);

    // 5 message-passing layers
    for (int l = 0; l < 5; l++) {
        k_gather_hs<<<NB_G, TPB>>>();
        int hasW = (l < 4) ? 1 : 0;
        k_gemm_fused<<<NV / TM, 128>>>(B[l],
                                       hasW ? W[l + 1] : W[0],
                                       Wout + (size_t)l * HID * 64,
                                       hasW, l == 0 ? 1 : 0);
    }

    // final aggregation straight into out (+bout)
    k_gather_out<<<NB_G, TPB>>>(out, bout);
}

// round 11
// speedup vs baseline: 1.3493x; 1.2781x over previous
#include <cuda_runtime.h>
#include <cuda_fp16.h>
#include <mma.h>

using namespace nvcuda;

#define NV 100000
#define NE 1600000
#define HID 64
#define FIN 256
#define TM 32
#define PADH 72
#define NBLK_SCAN 391   // ceil(NV/256)

// ---------------- scratch (static device globals) ---------------------------
__device__ float   g_ns[NV];
__device__ float   g_nd[NV];
__device__ int     g_odeg[NV];
__device__ int     g_indeg[NV];
__device__ int     g_rowptr[NV + 1];
__device__ int     g_cur[NV];
__device__ int     g_bsum[512];
__device__ int     g_boff[512];
__device__ int     g_esrc[NE];                   // src ids grouped by dst (CSR)
__device__ __half2 g_hs2[(size_t)NV * 32];       // fp16 message table (64 cols)
__device__ float   g_agg[(size_t)NV * HID];      // gather destination (fp32)
__device__ float   g_y[(size_t)NV * HID];        // accumulated out @ Wout (fp32)

// ---------------- degree / CSR build ----------------------------------------
__global__ void k_zero0() {
    int i = blockIdx.x * blockDim.x + threadIdx.x;
    if (i < NV) { g_odeg[i] = 0; g_indeg[i] = 0; }
}

__global__ void k_deg(const int* __restrict__ src, const int* __restrict__ dst) {
    int e = blockIdx.x * blockDim.x + threadIdx.x;
    if (e < NE) {
        atomicAdd(&g_odeg[src[e]], 1);
        atomicAdd(&g_indeg[dst[e]], 1);
    }
}

__global__ void k_norm() {
    int i = blockIdx.x * blockDim.x + threadIdx.x;
    if (i < NV) {
        g_ns[i] = rsqrtf(fmaxf((float)g_odeg[i], 1.f));
        g_nd[i] = rsqrtf(fmaxf((float)g_indeg[i], 1.f));
    }
}

__global__ void __launch_bounds__(256) k_scan1() {
    __shared__ int sm[256];
    int t = threadIdx.x;
    int i = blockIdx.x * 256 + t;
    int v = (i < NV) ? g_indeg[i] : 0;
    sm[t] = v;
    __syncthreads();
    #pragma unroll
    for (int ofs = 1; ofs < 256; ofs <<= 1) {
        int add = (t >= ofs) ? sm[t - ofs] : 0;
        __syncthreads();
        sm[t] += add;
        __syncthreads();
    }
    if (i < NV) g_rowptr[i] = sm[t] - v;
    if (t == 255) g_bsum[blockIdx.x] = sm[255];
}

__global__ void __launch_bounds__(512) k_scan2() {
    __shared__ int sm[512];
    int t = threadIdx.x;
    int v = (t < NBLK_SCAN) ? g_bsum[t] : 0;
    sm[t] = v;
    __syncthreads();
    #pragma unroll
    for (int ofs = 1; ofs < 512; ofs <<= 1) {
        int add = (t >= ofs) ? sm[t - ofs] : 0;
        __syncthreads();
        sm[t] += add;
        __syncthreads();
    }
    g_boff[t] = sm[t] - v;
}

__global__ void k_scan3() {
    int i = blockIdx.x * blockDim.x + threadIdx.x;
    if (i < NV) {
        int r = g_rowptr[i] + g_boff[i >> 8];
        g_rowptr[i] = r;
        g_cur[i] = r;
    }
    if (i == 0) g_rowptr[NV] = NE;
}

__global__ void k_fill(const int* __restrict__ src, const int* __restrict__ dst) {
    int e = blockIdx.x * blockDim.x + threadIdx.x;
    if (e < NE) {
        int pos = atomicAdd(&g_cur[dst[e]], 1);
        g_esrc[pos] = src[e];
    }
}

// ---------------- CSR gather hs (fp16 table -> fp32 accum) --------------------
__global__ void __launch_bounds__(256)
k_gather_hs() {
    int w = (blockIdx.x * 256 + threadIdx.x) >> 5;
    int lane = threadIdx.x & 31;
    if (w >= NV) return;
    int beg = g_rowptr[w], end = g_rowptr[w + 1];
    float2 acc = make_float2(0.f, 0.f);
    int e = beg;
    for (; e + 4 <= end; e += 4) {
        int s0 = g_esrc[e], s1 = g_esrc[e + 1], s2 = g_esrc[e + 2], s3 = g_esrc[e + 3];
        float2 v0 = __half22float2(g_hs2[(size_t)s0 * 32 + lane]);
        float2 v1 = __half22float2(g_hs2[(size_t)s1 * 32 + lane]);
        float2 v2 = __half22float2(g_hs2[(size_t)s2 * 32 + lane]);
        float2 v3 = __half22float2(g_hs2[(size_t)s3 * 32 + lane]);
        acc.x += (v0.x + v1.x) + (v2.x + v3.x);
        acc.y += (v0.y + v1.y) + (v2.y + v3.y);
    }
    for (; e < end; e++) {
        int s = g_esrc[e];
        float2 v = __half22float2(g_hs2[(size_t)s * 32 + lane]);
        acc.x += v.x; acc.y += v.y;
    }
    reinterpret_cast<float2*>(g_agg)[(size_t)w * 32 + lane] = acc;
}

// final: out[n] = bout + sum g_y[esrc[e]]   (fp32 table)
__global__ void __launch_bounds__(256)
k_gather_out(float* __restrict__ out, const float* __restrict__ bout) {
    int w = (blockIdx.x * 256 + threadIdx.x) >> 5;
    int lane = threadIdx.x & 31;
    if (w >= NV) return;
    int beg = g_rowptr[w], end = g_rowptr[w + 1];
    const float2* tb = reinterpret_cast<const float2*>(g_y);
    float2 acc = reinterpret_cast<const float2*>(bout)[lane];
    int e = beg;
    for (; e + 4 <= end; e += 4) {
        int s0 = g_esrc[e], s1 = g_esrc[e + 1], s2 = g_esrc[e + 2], s3 = g_esrc[e + 3];
        float2 v0 = tb[(size_t)s0 * 32 + lane];
        float2 v1 = tb[(size_t)s1 * 32 + lane];
        float2 v2 = tb[(size_t)s2 * 32 + lane];
        float2 v3 = tb[(size_t)s3 * 32 + lane];
        acc.x += (v0.x + v1.x) + (v2.x + v3.x);
        acc.y += (v0.y + v1.y) + (v2.y + v3.y);
    }
    for (; e < end; e++) {
        int s = g_esrc[e];
        float2 v = tb[(size_t)s * 32 + lane];
        acc.x += v.x; acc.y += v.y;
    }
    reinterpret_cast<float2*>(out)[(size_t)w * 32 + lane] = acc;
}

// ---------------- GEMM 0 (WMMA): hs = ns * (feats @ W0), K=256 ---------------
// M-tile 64, 4 warps; warp w owns col-tile w (16 cols), row tiles 0..3.
__global__ void __launch_bounds__(128)
k_gemm0(const float* __restrict__ feats, const float* __restrict__ W0) {
    __shared__ alignas(32) __half Ah[64][PADH];
    __shared__ alignas(32) __half Bh[64][PADH];
    __shared__ alignas(32) float  Cs[64][68];
    int t = threadIdx.x;
    int warp = t >> 5;
    int rowBase = blockIdx.x * 64;

    wmma::fragment<wmma::accumulator, 16, 16, 16, float> cf[4];
    #pragma unroll
    for (int i = 0; i < 4; i++) wmma::fill_fragment(cf[i], 0.0f);

    for (int kb = 0; kb < FIN; kb += 64) {
        #pragma unroll
        for (int i = 0; i < 8; i++) {               // A chunk 64x64 fp32->half
            int idx = t + i * 128;
            int m = idx >> 4, k4 = (idx & 15) * 4;
            int rc = rowBase + m; if (rc >= NV) rc = NV - 1;
            float4 a = *reinterpret_cast<const float4*>(feats + (size_t)rc * FIN + kb + k4);
            __half2* dst = reinterpret_cast<__half2*>(&Ah[m][k4]);
            dst[0] = __floats2half2_rn(a.x, a.y);
            dst[1] = __floats2half2_rn(a.z, a.w);
        }
        #pragma unroll
        for (int i = 0; i < 8; i++) {               // B chunk 64x64 fp32->half
            int idx = t + i * 128;
            int k = idx >> 4, c4 = (idx & 15) * 4;
            float4 b = *reinterpret_cast<const float4*>(W0 + (size_t)(kb + k) * HID + c4);
            __half2* dst = reinterpret_cast<__half2*>(&Bh[k][c4]);
            dst[0] = __floats2half2_rn(b.x, b.y);
            dst[1] = __floats2half2_rn(b.z, b.w);
        }
        __syncthreads();
        #pragma unroll
        for (int ks = 0; ks < 4; ks++) {
            wmma::fragment<wmma::matrix_b, 16, 16, 16, __half, wmma::row_major> bf;
            wmma::load_matrix_sync(bf, &Bh[ks * 16][warp * 16], PADH);
            #pragma unroll
            for (int rt = 0; rt < 4; rt++) {
                wmma::fragment<wmma::matrix_a, 16, 16, 16, __half, wmma::row_major> af;
                wmma::load_matrix_sync(af, &Ah[rt * 16][ks * 16], PADH);
                wmma::mma_sync(cf[rt], af, bf, cf[rt]);
            }
        }
        __syncthreads();
    }
    #pragma unroll
    for (int rt = 0; rt < 4; rt++)
        wmma::store_matrix_sync(&Cs[rt * 16][warp * 16], cf[rt], 68, wmma::mem_row_major);
    __syncthreads();
    #pragma unroll
    for (int i = 0; i < 8; i++) {
        int idx = t + i * 128;
        int m = idx >> 4, c4 = (idx & 15) * 4;
        int row = rowBase + m;
        if (row < NV) {
            float s = g_ns[row];
            float4 v = *reinterpret_cast<const float4*>(&Cs[m][c4]);
            __half2* hp = &g_hs2[(size_t)row * 32 + (c4 >> 1)];
            hp[0] = __floats2half2_rn(v.x * s, v.y * s);
            hp[1] = __floats2half2_rn(v.z * s, v.w * s);
        }
    }
}

// ---------------- fused layer GEMM (WMMA) ------------------------------------
// A = relu(agg*nd + b) fp16 in SMEM; C[32x128] = A @ [W | Wo].
// warp w: col-tile w (W side) + col-tile w (Wo side), row tiles 0,1.
__global__ void __launch_bounds__(128)
k_gemm_fused(const float* __restrict__ bias,
             const float* __restrict__ W,
             const float* __restrict__ Wo,
             int hasW, int firstY) {
    __shared__ alignas(32) __half Ah[TM][PADH];
    __shared__ alignas(32) __half Bwh[64][PADH];
    __shared__ alignas(32) __half Boh[64][PADH];
    __shared__ alignas(32) float  Cs[TM][132];
    int t = threadIdx.x;
    int warp = t >> 5;
    int rowBase = blockIdx.x * TM;

    #pragma unroll
    for (int i = 0; i < 4; i++) {                   // A 32x64 relu-transform -> half
        int idx = t + i * 128;
        int m = idx >> 4, k4 = (idx & 15) * 4;
        int row = rowBase + m;
        float4 v = *reinterpret_cast<const float4*>(g_agg + (size_t)row * HID + k4);
        float nd = g_nd[row];
        float4 bb = *reinterpret_cast<const float4*>(bias + k4);
        __half2* dst = reinterpret_cast<__half2*>(&Ah[m][k4]);
        dst[0] = __floats2half2_rn(fmaxf(v.x * nd + bb.x, 0.f), fmaxf(v.y * nd + bb.y, 0.f));
        dst[1] = __floats2half2_rn(fmaxf(v.z * nd + bb.z, 0.f), fmaxf(v.w * nd + bb.w, 0.f));
    }
    if (hasW) {
        #pragma unroll
        for (int i = 0; i < 8; i++) {
            int idx = t + i * 128;
            int k = idx >> 4, c4 = (idx & 15) * 4;
            float4 b = *reinterpret_cast<const float4*>(W + (size_t)k * HID + c4);
            __half2* dst = reinterpret_cast<__half2*>(&Bwh[k][c4]);
            dst[0] = __floats2half2_rn(b.x, b.y);
            dst[1] = __floats2half2_rn(b.z, b.w);
        }
    }
    #pragma unroll
    for (int i = 0; i < 8; i++) {
        int idx = t + i * 128;
        int k = idx >> 4, c4 = (idx & 15) * 4;
        float4 b = *reinterpret_cast<const float4*>(Wo + (size_t)k * HID + c4);
        __half2* dst = reinterpret_cast<__half2*>(&Boh[k][c4]);
        dst[0] = __floats2half2_rn(b.x, b.y);
        dst[1] = __floats2half2_rn(b.z, b.w);
    }
    __syncthreads();

    wmma::fragment<wmma::accumulator, 16, 16, 16, float> cw[2], co[2];
    #pragma unroll
    for (int i = 0; i < 2; i++) {
        wmma::fill_fragment(cw[i], 0.0f);
        wmma::fill_fragment(co[i], 0.0f);
    }

    #pragma unroll
    for (int ks = 0; ks < 4; ks++) {
        wmma::fragment<wmma::matrix_a, 16, 16, 16, __half, wmma::row_major> af[2];
        #pragma unroll
        for (int rt = 0; rt < 2; rt++)
            wmma::load_matrix_sync(af[rt], &Ah[rt * 16][ks * 16], PADH);
        if (hasW) {
            wmma::fragment<wmma::matrix_b, 16, 16, 16, __half, wmma::row_major> bw;
            wmma::load_matrix_sync(bw, &Bwh[ks * 16][warp * 16], PADH);
            #pragma unroll
            for (int rt = 0; rt < 2; rt++)
                wmma::mma_sync(cw[rt], af[rt], bw, cw[rt]);
        }
        wmma::fragment<wmma::matrix_b, 16, 16, 16, __half, wmma::row_major> bo;
        wmma::load_matrix_sync(bo, &Boh[ks * 16][warp * 16], PADH);
        #pragma unroll
        for (int rt = 0; rt < 2; rt++)
            wmma::mma_sync(co[rt], af[rt], bo, co[rt]);
    }

    #pragma unroll
    for (int rt = 0; rt < 2; rt++) {
        if (hasW)
            wmma::store_matrix_sync(&Cs[rt * 16][warp * 16], cw[rt], 132, wmma::mem_row_major);
        wmma::store_matrix_sync(&Cs[rt * 16][64 + warp * 16], co[rt], 132, wmma::mem_row_major);
    }
    __syncthreads();

    if (hasW) {
        #pragma unroll
        for (int i = 0; i < 4; i++) {
            int idx = t + i * 128;
            int m = idx >> 4, c4 = (idx & 15) * 4;
            int row = rowBase + m;
            float s = g_ns[row];
            float4 v = *reinterpret_cast<const float4*>(&Cs[m][c4]);
            __half2* hp = &g_hs2[(size_t)row * 32 + (c4 >> 1)];
            hp[0] = __floats2half2_rn(v.x * s, v.y * s);
            hp[1] = __floats2half2_rn(v.z * s, v.w * s);
        }
    }
    #pragma unroll
    for (int i = 0; i < 4; i++) {
        int idx = t + i * 128;
        int m = idx >> 4, c4 = (idx & 15) * 4;
        int row = rowBase + m;
        float4 v = *reinterpret_cast<const float4*>(&Cs[m][64 + c4]);
        float4* yp = reinterpret_cast<float4*>(g_y + (size_t)row * HID + c4);
        if (firstY) {
            *yp = v;
        } else {
            float4 a = *yp;
            a.x += v.x; a.y += v.y; a.z += v.z; a.w += v.w;
            *yp = a;
        }
    }
}

// ---------------- launch ------------------------------------------------------
extern "C" void kernel_launch(void* const* d_in, const int* in_sizes, int n_in,
                              void* d_out, int out_size) {
    const float* feats = (const float*)d_in[0];
    const int*   src   = (const int*)d_in[1];
    const int*   dst   = (const int*)d_in[2];
    const float* W[5];
    const float* B[5];
    for (int i = 0; i < 5; i++) {
        W[i] = (const float*)d_in[3 + 2 * i];
        B[i] = (const float*)d_in[4 + 2 * i];
    }
    const float* Wout = (const float*)d_in[13];
    const float* bout = (const float*)d_in[14];
    float* out = (float*)d_out;

    const int TPB = 256;
    const int NB_V = (NV + TPB - 1) / TPB;      // 391
    const int NB_E = (NE + TPB - 1) / TPB;      // 6250
    const int NB_G = (NV * 32 + TPB - 1) / TPB; // 12500 (warp per node)

    // prologue (gemm0 kept in the ncu-sampled 4th slot)
    k_zero0<<<NB_V, TPB>>>();
    k_deg<<<NB_E, TPB>>>(src, dst);
    k_norm<<<NB_V, TPB>>>();
    k_gemm0<<<(NV + 63) / 64, 128>>>(feats, W[0]);

    // CSR build (independent of gemm0)
    k_scan1<<<NB_V, 256>>>();
    k_scan2<<<1, 512>>>();
    k_scan3<<<NB_V, TPB>>>();
    k_fill<<<NB_E, TPB>>>(src, dst);

    // 5 message-passing layers
    for (int l = 0; l < 5; l++) {
        k_gather_hs<<<NB_G, TPB>>>();
        int hasW = (l < 4) ? 1 : 0;
        k_gemm_fused<<<NV / TM, 128>>>(B[l],
                                       hasW ? W[l + 1] : W[0],
                                       Wout + (size_t)l * HID * 64,
                                       hasW, l == 0 ? 1 : 0);
    }

    // final aggregation straight into out (+bout)
    k_gather_out<<<NB_G, TPB>>>(out, bout);
}